// round 1
// baseline (speedup 1.0000x reference)
#include <cuda_runtime.h>

// GraphConv: out = relu( segment_sum(feature[src] -> dst) @ W^T + b )
// feature: [50000,128] f32, W: [128,128] f32, b: [128] f32, edge_index: [2,800000] i32
// out: [50000,128] f32

constexpr int N_NODES = 50000;
constexpr int N_EDGES = 800000;
constexpr int D       = 128;

// scratch: aggregated features (25.6 MB, static device global — no allocs)
__device__ float g_agg[N_NODES * D];

// ---------------------------------------------------------------------------
// Kernel 1: zero the aggregation buffer
// ---------------------------------------------------------------------------
__global__ void __launch_bounds__(256) zero_agg_kernel() {
    int i = blockIdx.x * blockDim.x + threadIdx.x;
    if (i < N_NODES * D / 4)
        reinterpret_cast<float4*>(g_agg)[i] = make_float4(0.f, 0.f, 0.f, 0.f);
}

// ---------------------------------------------------------------------------
// Kernel 2: scatter-add  g_agg[dst] += feature[src]
// One thread per (edge, float4-chunk): 800k * 32 = 25.6M threads.
// Vector float4 atomics (sm_90+) cut RED op count 4x.
// ---------------------------------------------------------------------------
__device__ __forceinline__ void atomic_add4(float4* addr, float4 v) {
#if defined(__CUDA_ARCH__) && __CUDA_ARCH__ >= 900
    atomicAdd(addr, v);
#else
    float* f = reinterpret_cast<float*>(addr);
    atomicAdd(f + 0, v.x);
    atomicAdd(f + 1, v.y);
    atomicAdd(f + 2, v.z);
    atomicAdd(f + 3, v.w);
#endif
}

__global__ void __launch_bounds__(256) scatter_add_kernel(
    const float4* __restrict__ feat4, const int* __restrict__ ei)
{
    int idx = blockIdx.x * blockDim.x + threadIdx.x;
    if (idx >= N_EDGES * 32) return;
    int e = idx >> 5;          // edge id (32 consecutive threads share it)
    int c = idx & 31;          // float4 chunk within the 128-float row
    int src = __ldg(&ei[e]);               // edge_index[0][e]
    int dst = __ldg(&ei[N_EDGES + e]);     // edge_index[1][e]
    float4 v = feat4[src * 32 + c];
    atomic_add4(reinterpret_cast<float4*>(g_agg) + dst * 32 + c, v);
}

// ---------------------------------------------------------------------------
// Kernel 3: out = relu( g_agg @ W^T + b )
// Classic smem-tiled SGEMM: BM=64, BN=128 (full N), BK=16, 128 threads,
// 8x8 register tile per thread. A and W stored k-transposed in smem so both
// operand reads are conflict-light float4 LDS.
// ---------------------------------------------------------------------------
constexpr int BM = 64;
constexpr int BN = 128;
constexpr int BK = 16;

__global__ void __launch_bounds__(128) gemm_bias_relu_kernel(
    const float* __restrict__ Wm, const float* __restrict__ bias,
    float* __restrict__ out)
{
    __shared__ float As[BK][BM];   // As[k][m]  = agg[m][k]
    __shared__ float Bs[BK][BN];   // Bs[k][n]  = W[n][k]

    const int t  = threadIdx.x;
    const int m0 = blockIdx.x * BM;
    const int tm = (t >> 4) * 8;   // 0..56  (row offset within tile)
    const int tn = (t & 15) * 8;   // 0..120 (col offset within tile)

    float acc[8][8];
#pragma unroll
    for (int i = 0; i < 8; i++)
#pragma unroll
        for (int j = 0; j < 8; j++) acc[i][j] = 0.f;

    for (int k0 = 0; k0 < D; k0 += BK) {
        // ---- load A tile (64 rows x 16 k), transpose into As[k][m] ----
#pragma unroll
        for (int i = 0; i < 2; i++) {
            int lin = t * 2 + i;        // 0..255
            int row = lin >> 2;         // 0..63
            int kq  = lin & 3;          // which float4 of the 16-wide k chunk
            int m   = m0 + row;
            float4 v = make_float4(0.f, 0.f, 0.f, 0.f);
            if (m < N_NODES)
                v = reinterpret_cast<const float4*>(g_agg + m * D + k0)[kq];
            As[kq * 4 + 0][row] = v.x;
            As[kq * 4 + 1][row] = v.y;
            As[kq * 4 + 2][row] = v.z;
            As[kq * 4 + 3][row] = v.w;
        }
        // ---- load W tile (all 128 rows n x 16 k), transpose into Bs[k][n] ----
        {
            const float4* wrow = reinterpret_cast<const float4*>(Wm + t * D + k0);
#pragma unroll
            for (int q = 0; q < 4; q++) {
                float4 v = wrow[q];
                Bs[q * 4 + 0][t] = v.x;
                Bs[q * 4 + 1][t] = v.y;
                Bs[q * 4 + 2][t] = v.z;
                Bs[q * 4 + 3][t] = v.w;
            }
        }
        __syncthreads();

#pragma unroll
        for (int kk = 0; kk < BK; kk++) {
            float4 a0 = *reinterpret_cast<const float4*>(&As[kk][tm]);
            float4 a1 = *reinterpret_cast<const float4*>(&As[kk][tm + 4]);
            float4 b0 = *reinterpret_cast<const float4*>(&Bs[kk][tn]);
            float4 b1 = *reinterpret_cast<const float4*>(&Bs[kk][tn + 4]);
            float a[8] = {a0.x, a0.y, a0.z, a0.w, a1.x, a1.y, a1.z, a1.w};
            float bb[8] = {b0.x, b0.y, b0.z, b0.w, b1.x, b1.y, b1.z, b1.w};
#pragma unroll
            for (int i = 0; i < 8; i++)
#pragma unroll
                for (int j = 0; j < 8; j++)
                    acc[i][j] = fmaf(a[i], bb[j], acc[i][j]);
        }
        __syncthreads();
    }

    // ---- epilogue: + bias, relu, store ----
    float bv[8];
#pragma unroll
    for (int j = 0; j < 8; j++) bv[j] = __ldg(&bias[tn + j]);

#pragma unroll
    for (int i = 0; i < 8; i++) {
        int m = m0 + tm + i;
        if (m < N_NODES) {
            float4 r0, r1;
            r0.x = fmaxf(acc[i][0] + bv[0], 0.f);
            r0.y = fmaxf(acc[i][1] + bv[1], 0.f);
            r0.z = fmaxf(acc[i][2] + bv[2], 0.f);
            r0.w = fmaxf(acc[i][3] + bv[3], 0.f);
            r1.x = fmaxf(acc[i][4] + bv[4], 0.f);
            r1.y = fmaxf(acc[i][5] + bv[5], 0.f);
            r1.z = fmaxf(acc[i][6] + bv[6], 0.f);
            r1.w = fmaxf(acc[i][7] + bv[7], 0.f);
            float4* o = reinterpret_cast<float4*>(out + m * D + tn);
            o[0] = r0;
            o[1] = r1;
        }
    }
}

// ---------------------------------------------------------------------------
extern "C" void kernel_launch(void* const* d_in, const int* in_sizes, int n_in,
                              void* d_out, int out_size)
{
    const float* feature = (const float*)d_in[0];   // [50000,128]
    const float* Wm      = (const float*)d_in[1];   // [128,128]
    const float* bias    = (const float*)d_in[2];   // [128]
    const int*   ei      = (const int*)  d_in[3];   // [2,800000]
    float*       out     = (float*)d_out;           // [50000,128]

    (void)in_sizes; (void)n_in; (void)out_size;

    {
        int n = N_NODES * D / 4;
        zero_agg_kernel<<<(n + 255) / 256, 256>>>();
    }
    {
        long long total = (long long)N_EDGES * 32;
        int blocks = (int)((total + 255) / 256);
        scatter_add_kernel<<<blocks, 256>>>(
            reinterpret_cast<const float4*>(feature), ei);
    }
    {
        int blocks = (N_NODES + BM - 1) / BM;
        gemm_bias_relu_kernel<<<blocks, 128>>>(Wm, bias, out);
    }
}